// round 7
// baseline (speedup 1.0000x reference)
#include <cuda_runtime.h>
#include <cuda_bf16.h>
#include <cstdint>

#define B_SZ   128
#define NNODES 2047
#define LEAVES 1024
#define DIN    512
#define NL     64
#define MROWS  (B_SZ * NNODES)          // 262016

typedef unsigned long long u64;

// ---------------- device scratch (static; no allocations) ----------------
__device__ float g_emis[(size_t)B_SZ * NNODES * NL];   // 67 MB
__device__ float g_bufA[(size_t)B_SZ * 512 * NL];      // odd levels
__device__ float g_bufB[(size_t)B_SZ * 256 * NL];      // even levels
__device__ u64   g_w2[32 * NL];                        // [kp][l] packed exp(trans)
__device__ uint4 g_Wfrag[32 * 8 * 32];                 // [kstep][ntile][lane] {bhi0,bhi1,blo0,blo1}

// ---------------- packed helpers ----------------
__device__ __forceinline__ u64 fma2(u64 a, u64 b, u64 c) {
    u64 d; asm("fma.rn.f32x2 %0, %1, %2, %3;" : "=l"(d) : "l"(a), "l"(b), "l"(c)); return d;
}
__device__ __forceinline__ u64 pack2(float lo, float hi) {
    u64 d; asm("mov.b64 %0, {%1, %2};" : "=l"(d) : "f"(lo), "f"(hi)); return d;
}
__device__ __forceinline__ float2 unpack2(u64 v) {
    float2 r; asm("mov.b64 {%0, %1}, %2;" : "=f"(r.x), "=f"(r.y) : "l"(v)); return r;
}
// single-rounded bf16x2 pack: low half = x0 (even k), high half = x1 (odd k)
__device__ __forceinline__ uint32_t cvt_bf2(float x0, float x1) {
    uint32_t h;
    asm("cvt.rn.satfinite.bf16x2.f32 %0, %1, %2;" : "=r"(h) : "f"(x1), "f"(x0));
    return h;
}
// bf16x2 hi/lo split (used for W precompute only)
__device__ __forceinline__ void cvt_hilo(float x0, float x1, uint32_t& h, uint32_t& l) {
    asm("cvt.rn.satfinite.bf16x2.f32 %0, %1, %2;" : "=r"(h) : "f"(x1), "f"(x0));
    float r0 = x0 - __uint_as_float(h << 16);
    float r1 = x1 - __uint_as_float(h & 0xffff0000u);
    asm("cvt.rn.satfinite.bf16x2.f32 %0, %1, %2;" : "=r"(l) : "f"(r1), "f"(r0));
}
__device__ __forceinline__ void mma16816(float& d0, float& d1, float& d2, float& d3,
                                         uint32_t a0, uint32_t a1, uint32_t a2, uint32_t a3,
                                         uint32_t b0, uint32_t b1) {
    asm("mma.sync.aligned.m16n8k16.row.col.f32.bf16.bf16.f32 "
        "{%0,%1,%2,%3}, {%4,%5,%6,%7}, {%8,%9}, {%0,%1,%2,%3};"
        : "+f"(d0), "+f"(d1), "+f"(d2), "+f"(d3)
        : "r"(a0), "r"(a1), "r"(a2), "r"(a3), "r"(b0), "r"(b1));
}

// ---------------- init: exp(trans) pairs + W b-fragments (hi/lo) ----------------
__global__ void init_kernel(const float* __restrict__ trans, const float* __restrict__ W) {
    int i = blockIdx.x * blockDim.x + threadIdx.x;
    if (i < 2048) {
        int kp = i >> 6, l = i & 63;
        float a = expf(trans[l * NL + 2 * kp]);
        float b = expf(trans[l * NL + 2 * kp + 1]);
        g_w2[kp * NL + l] = pack2(a, b);
    }
    int j = i - 2048;
    if (j >= 0 && j < 32 * 8 * 32) {
        int lane = j & 31, t = (j >> 5) & 7, s = j >> 8;
        int n  = t * 8 + (lane >> 2);
        int k0 = s * 16 + (lane & 3) * 2;
        float w00 = W[k0 * NL + n],       w01 = W[(k0 + 1) * NL + n];
        float w10 = W[(k0 + 8) * NL + n], w11 = W[(k0 + 9) * NL + n];
        uint32_t bh0, bl0, bh1, bl1;
        cvt_hilo(w00, w01, bh0, bl0);
        cvt_hilo(w10, w11, bh1, bl1);
        g_Wfrag[j] = make_uint4(bh0, bh1, bl0, bl1);
    }
}

// ---------------- HMMA emission GEMM: emis = hidden @ W + b ----------------
// CTA = 512 rows, 16 warps x 32 rows (2 m16 tiles). 2 MMAs/tile: A*(Whi) + A*(Wlo).
#define GS_TOTAL (131072 + 256)

extern __shared__ char dynsm[];

__global__ __launch_bounds__(512) void gemm_kernel(
    const float* __restrict__ A, const float* __restrict__ bias,
    float* __restrict__ out)
{
    uint4* Wsm = (uint4*)dynsm;
    float* bsm = (float*)(dynsm + 131072);
    int tid = threadIdx.x;
    {
        const uint4* src = g_Wfrag;
        for (int i = tid; i < 8192; i += 512) Wsm[i] = src[i];
        if (tid < NL) bsm[tid] = bias[tid];
    }
    __syncthreads();

    int lane = tid & 31, w = tid >> 5;
    long rowbase = (long)blockIdx.x * 512 + w * 32;
    int qr = lane >> 2;            // 0..7
    int qk = (lane & 3) * 2;       // 0,2,4,6

    // 4 row pointers: [rt*2 + rh] -> row rowbase + rt*16 + rh*8 + qr (clamped)
    const float* aptr[4];
#pragma unroll
    for (int rt = 0; rt < 2; ++rt)
#pragma unroll
        for (int rh = 0; rh < 2; ++rh) {
            long r = rowbase + rt * 16 + rh * 8 + qr;
            if (r > MROWS - 1) r = MROWS - 1;
            aptr[rt * 2 + rh] = A + r * DIN + qk;
        }

    float acc[2][8][4];
#pragma unroll
    for (int rt = 0; rt < 2; ++rt)
#pragma unroll
        for (int t = 0; t < 8; ++t)
#pragma unroll
            for (int e = 0; e < 4; ++e) acc[rt][t][e] = 0.f;

    float2 cur[4][2], nxt[4][2];
#pragma unroll
    for (int p = 0; p < 4; ++p) {
        cur[p][0] = *(const float2*)(aptr[p]);
        cur[p][1] = *(const float2*)(aptr[p] + 8);
    }

#pragma unroll 1
    for (int s = 0; s < 32; ++s) {
        if (s < 31) {
#pragma unroll
            for (int p = 0; p < 4; ++p) {
                nxt[p][0] = *(const float2*)(aptr[p] + (s + 1) * 16);
                nxt[p][1] = *(const float2*)(aptr[p] + (s + 1) * 16 + 8);
            }
        }
        // convert A fragments (single bf16 rounding)
        uint32_t ah[2][4];
#pragma unroll
        for (int rt = 0; rt < 2; ++rt) {
            ah[rt][0] = cvt_bf2(cur[2*rt][0].x,   cur[2*rt][0].y);
            ah[rt][1] = cvt_bf2(cur[2*rt+1][0].x, cur[2*rt+1][0].y);
            ah[rt][2] = cvt_bf2(cur[2*rt][1].x,   cur[2*rt][1].y);
            ah[rt][3] = cvt_bf2(cur[2*rt+1][1].x, cur[2*rt+1][1].y);
        }
        // B fragments from smem + 2-product MMA (W split hi/lo)
#pragma unroll
        for (int t = 0; t < 8; ++t) {
            uint4 wb = Wsm[(s * 8 + t) * 32 + lane];
#pragma unroll
            for (int rt = 0; rt < 2; ++rt) {
                mma16816(acc[rt][t][0], acc[rt][t][1], acc[rt][t][2], acc[rt][t][3],
                         ah[rt][0], ah[rt][1], ah[rt][2], ah[rt][3], wb.x, wb.y);  // A*Whi
                mma16816(acc[rt][t][0], acc[rt][t][1], acc[rt][t][2], acc[rt][t][3],
                         ah[rt][0], ah[rt][1], ah[rt][2], ah[rt][3], wb.z, wb.w);  // A*Wlo
            }
        }
#pragma unroll
        for (int p = 0; p < 4; ++p) { cur[p][0] = nxt[p][0]; cur[p][1] = nxt[p][1]; }
    }

    // epilogue: bias + store
#pragma unroll
    for (int rt = 0; rt < 2; ++rt)
#pragma unroll
        for (int rh = 0; rh < 2; ++rh) {
            long r = rowbase + rt * 16 + rh * 8 + qr;
            if (r < MROWS) {
                float* orow = out + r * NL;
#pragma unroll
                for (int t = 0; t < 8; ++t) {
                    int c = t * 8 + qk;
                    float2 v;
                    v.x = acc[rt][t][rh * 2 + 0] + bsm[c];
                    v.y = acc[rt][t][rh * 2 + 1] + bsm[c + 1];
                    *(float2*)(orow + c) = v;
                }
            }
        }
}

// ---------------- fused tree kernel (unchanged; near fma floor) ----------------
#define E2_PITCH 257
#define TREE_SMEM_BYTES ((2048 + 32 * E2_PITCH) * 8 + 256 * 4)

__global__ __launch_bounds__(512) void tree_kernel(
    const float* __restrict__ emis, float* __restrict__ bufA,
    float* __restrict__ bufB, float* __restrict__ outg)
{
    u64* smem = (u64*)dynsm;
    u64* W2s = smem;
    u64* E2s = smem + 2048;
    float* mbuf = (float*)(smem + 2048 + 32 * E2_PITCH);

    int t = threadIdx.x;
    int b = blockIdx.x;

    for (int i = t; i < 2048; i += 512) W2s[i] = g_w2[i];
    for (int i = t; i < 32 * E2_PITCH; i += 512) E2s[i] = 0ull;
    if (t < 256) mbuf[t] = 0.f;
    __syncthreads();

    const float* emisb = emis + (size_t)b * NNODES * NL;
    const float* prev  = emisb + (size_t)(LEAVES - 1) * NL;
    float* bufAb = bufA + (size_t)b * 512 * NL;
    float* bufBb = bufB + (size_t)b * 256 * NL;

    int cvg = t & 31, lg = t >> 5;
    int sub = t & 3,  cquad = t >> 2;

    for (int d = 9; d >= 0; --d) {
        int n = 1 << d;
        const float* emisLvl = emisb + (size_t)(n - 1) * NL;
        float* outLvl = (d == 0) ? (outg + (size_t)b * NL)
                                 : ((d & 1) ? bufAb : bufBb);
        int ntiles = (n + 127) >> 7;
        for (int tile = 0; tile < ntiles; ++tile) {
            int i0 = tile << 7;
            int NT = n - i0; if (NT > 128) NT = 128;
            int ncv = 2 * NT;

#pragma unroll
            for (int co = 0; co < 256; co += 128) {
                int c = co + cquad;
                bool valid = c < ncv;
                int cc = valid ? c : 0;
                const float* src = prev + (size_t)(i0 * 2 + cc) * NL + sub * 16;
                float4 v0 = *(const float4*)(src);
                float4 v1 = *(const float4*)(src + 4);
                float4 v2 = *(const float4*)(src + 8);
                float4 v3 = *(const float4*)(src + 12);
                float vv[16] = {v0.x, v0.y, v0.z, v0.w, v1.x, v1.y, v1.z, v1.w,
                                v2.x, v2.y, v2.z, v2.w, v3.x, v3.y, v3.z, v3.w};
                float m = vv[0];
#pragma unroll
                for (int j = 1; j < 16; ++j) m = fmaxf(m, vv[j]);
                m = fmaxf(m, __shfl_xor_sync(0xffffffffu, m, 1));
                m = fmaxf(m, __shfl_xor_sync(0xffffffffu, m, 2));
                if (valid) {
#pragma unroll
                    for (int j = 0; j < 8; ++j) {
                        float e0 = __expf(vv[2 * j] - m);
                        float e1 = __expf(vv[2 * j + 1] - m);
                        E2s[(sub * 8 + j) * E2_PITCH + c] = pack2(e0, e1);
                    }
                    if (sub == 0) mbuf[c] = m;
                }
            }
            __syncthreads();

            u64 acc[8][4];
#pragma unroll
            for (int i = 0; i < 8; ++i)
#pragma unroll
                for (int j = 0; j < 4; ++j) acc[i][j] = 0ull;

#pragma unroll 2
            for (int kp = 0; kp < 32; ++kp) {
                const u64* er = E2s + kp * E2_PITCH + cvg;
                const u64* wr = W2s + kp * NL + lg;
                u64 w0 = wr[0], w1 = wr[16], w2v = wr[32], w3 = wr[48];
#pragma unroll
                for (int i = 0; i < 8; ++i) {
                    u64 e = er[32 * i];
                    acc[i][0] = fma2(e, w0,  acc[i][0]);
                    acc[i][1] = fma2(e, w1,  acc[i][1]);
                    acc[i][2] = fma2(e, w2v, acc[i][2]);
                    acc[i][3] = fma2(e, w3,  acc[i][3]);
                }
            }

            bool isLeft = (cvg & 1) == 0;
#pragma unroll
            for (int i = 0; i < 8; ++i) {
                int cv = cvg + 32 * i;
                float mv = mbuf[cv];
#pragma unroll
                for (int j = 0; j < 4; ++j) {
                    float2 u = unpack2(acc[i][j]);
                    float lse = __logf(u.x + u.y) + mv;
                    float oth = __shfl_xor_sync(0xffffffffu, lse, 1);
                    if (isLeft && cv < ncv) {
                        int node = i0 + (cv >> 1);
                        int l = lg + 16 * j;
                        outLvl[(size_t)node * NL + l] =
                            emisLvl[(size_t)node * NL + l] + lse + oth;
                    }
                }
            }
            __syncthreads();
        }
        prev = outLvl;
    }
}

// ---------------- launch ----------------
extern "C" void kernel_launch(void* const* d_in, const int* in_sizes, int n_in,
                              void* d_out, int out_size)
{
    const float* hidden = (const float*)d_in[0];
    const float* W      = (const float*)d_in[1];
    const float* bias   = (const float*)d_in[2];
    const float* trans  = (const float*)d_in[3];
    float* out = (float*)d_out;

    float *emis, *bufA, *bufB;
    cudaGetSymbolAddress((void**)&emis, g_emis);
    cudaGetSymbolAddress((void**)&bufA, g_bufA);
    cudaGetSymbolAddress((void**)&bufB, g_bufB);

    init_kernel<<<(2048 + 32 * 8 * 32 + 255) / 256, 256>>>(trans, W);

    cudaFuncSetAttribute(gemm_kernel, cudaFuncAttributeMaxDynamicSharedMemorySize, GS_TOTAL);
    gemm_kernel<<<(MROWS + 511) / 512, 512, GS_TOTAL>>>(hidden, bias, emis);

    cudaFuncSetAttribute(tree_kernel, cudaFuncAttributeMaxDynamicSharedMemorySize, TREE_SMEM_BYTES);
    tree_kernel<<<B_SZ, 512, TREE_SMEM_BYTES>>>(emis, bufA, bufB, out);
}